// round 7
// baseline (speedup 1.0000x reference)
#include <cuda_runtime.h>

// FeatureFuser: out = sigmoid( last-write-wins(sampling_map, refined[k] over window_k) )
// B=8, TOP_K=4, C=32, H=W=256, GRID=4 (cell 64x64), WINDOW=3 cells (192x192, clipped).
//
// Per output pixel exactly one source is read: refined[b, k_win, c, h, w] where
// k_win = max k whose window contains (h,w), else sampling_map[b,c,h,w].
//
// Warp-stride iteration: iteration i of thread tid handles float4 index
//   blockBase + i*256 + tid  -> every LDG.128/STG.128 is a contiguous 512B warp access.
// w4 = tid & 63 is invariant per thread; only h varies (h = hbase + 4*i), so
// x-window predicates and w4-folded base pointers are hoisted out of the loop.
//
// V_=4 + __launch_bounds__(256,8): keeps regs <= 32 -> full occupancy; this
// kernel is latency-bound, warps-in-flight beat instruction minimization (R6 lesson).
//
// regions arrive as int32 (JAX x64 disabled downcasts the int64 request).

#define B_      8
#define K_      4
#define C_      32
#define H_      256
#define W_      256
#define W4_     (W_/4)
#define PLANE4  (H_*W_/4)      // 16384 float4s per (b,c) plane
#define V_      4              // float4s per thread, warp-strided

__device__ __forceinline__ float fast_sigmoid(float x) {
    float t;
    asm("tanh.approx.f32 %0, %1;" : "=f"(t) : "f"(0.5f * x));
    return fmaf(0.5f, t, 0.5f);
}

__global__ void __launch_bounds__(256, 8)
feature_fuser_kernel(const float* __restrict__ smap,
                     const float* __restrict__ rmap,
                     const int* __restrict__ regions,
                     float* __restrict__ out)
{
    const int tid = threadIdx.x;
    const int w4  = tid & (W4_ - 1);                 // invariant per thread
    const int blockBase = blockIdx.x * (256 * V_);   // float4 index
    const int bc = blockBase >> 14;                  // uniform per block
    const int c  = bc & (C_ - 1);
    const int b  = bc >> 5;
    const int hbase = ((blockBase >> 6) & (H_ - 1)) + (tid >> 6);

    // Hoisted per-k state: y-range and x-predicate (x fixed per thread).
    int ys[K_]; unsigned ylen[K_]; bool xok[K_];
    #pragma unroll
    for (int k = 0; k < K_; ++k) {
        ys[k]   = __ldg(&regions[(b * K_ + k) * 2 + 0]) << 6;
        int xs4 =  __ldg(&regions[(b * K_ + k) * 2 + 1]) << 4;   // float4 units
        ylen[k] = (unsigned)(min(ys[k] + 192, H_) - ys[k]);
        xok[k]  = (unsigned)(w4 - xs4) < (unsigned)(min(xs4 + 48, W4_) - xs4);
    }

    // Per-k source base pointers with w4 folded in.
    const float4* s4 = reinterpret_cast<const float4*>(smap) + (size_t)bc * PLANE4 + w4;
    const float4* r4 = reinterpret_cast<const float4*>(rmap)
                     + ((size_t)(b * K_) * C_ + c) * PLANE4 + w4;

    float4 v[V_];
    #pragma unroll
    for (int i = 0; i < V_; ++i) {
        int h = hbase + 4 * i;
        const float4* p = s4;
        #pragma unroll
        for (int k = 0; k < K_; ++k) {               // ascending: last write wins
            bool inside = xok[k] & ((unsigned)(h - ys[k]) < ylen[k]);
            const float4* pk = r4 + (size_t)k * (C_ * PLANE4);
            p = inside ? pk : p;
        }
        v[i] = __ldg(p + h * W4_);                   // MLP=4, front-batched
    }

    float4* o4 = reinterpret_cast<float4*>(out) + blockBase + tid;
    #pragma unroll
    for (int i = 0; i < V_; ++i) {
        v[i].x = fast_sigmoid(v[i].x);
        v[i].y = fast_sigmoid(v[i].y);
        v[i].z = fast_sigmoid(v[i].z);
        v[i].w = fast_sigmoid(v[i].w);
        o4[i * 256] = v[i];
    }
}

extern "C" void kernel_launch(void* const* d_in, const int* in_sizes, int n_in,
                              void* d_out, int out_size)
{
    const float* smap    = (const float*)d_in[0];
    const float* rmap    = (const float*)d_in[1];
    const int*   regions = (const int*)d_in[2];
    float*       out     = (float*)d_out;

    const int total4  = B_ * C_ * H_ * W_ / 4;       // 4,194,304 float4s
    const int threads = 256;
    const int blocks  = total4 / (threads * V_);     // 4096
    feature_fuser_kernel<<<blocks, threads>>>(smap, rmap, regions, out);
}

// round 8
// speedup vs baseline: 1.0860x; 1.0860x over previous
#include <cuda_runtime.h>

// FeatureFuser: out = sigmoid( last-write-wins(sampling_map, refined[k] over window_k) )
// B=8, TOP_K=4, C=32, H=W=256, GRID=4 (cell 64x64), WINDOW=3 cells (192x192, clipped).
//
// Per output pixel exactly one source is read: refined[b, k_win, c, h, w] where
// k_win = max k whose window contains (h,w), else sampling_map[b,c,h,w].
//
// Warp-stride iteration: iteration i of thread tid handles float4 index
//   blockBase + i*256 + tid  -> every LDG.128/STG.128 is a contiguous 512B warp access.
// w4 = tid & 63 is invariant per thread; only h varies (h = hbase + 4*i), so
// x-window predicates and w4-folded base pointers are hoisted out of the loop.
//
// V_=4 + __launch_bounds__(256,8): regs <= 32 -> full occupancy (R6 lesson:
// latency-bound, warps-in-flight beat instruction minimization).
//
// Output stores are st.global.cs (evict-first): output is never re-read, so
// keep its 67 MB out of L2 and preserve source-tensor residency across graph
// replays (R5-R7 show ~50 MB/launch of reads served from L2).
//
// regions arrive as int32 (JAX x64 disabled downcasts the int64 request).

#define B_      8
#define K_      4
#define C_      32
#define H_      256
#define W_      256
#define W4_     (W_/4)
#define PLANE4  (H_*W_/4)      // 16384 float4s per (b,c) plane
#define V_      4              // float4s per thread, warp-strided

__device__ __forceinline__ float fast_sigmoid(float x) {
    float t;
    asm("tanh.approx.f32 %0, %1;" : "=f"(t) : "f"(0.5f * x));
    return fmaf(0.5f, t, 0.5f);
}

__device__ __forceinline__ void stcs4(float4* p, float4 v) {
    asm volatile("st.global.cs.v4.f32 [%0], {%1,%2,%3,%4};"
                 :: "l"(p), "f"(v.x), "f"(v.y), "f"(v.z), "f"(v.w) : "memory");
}

__global__ void __launch_bounds__(256, 8)
feature_fuser_kernel(const float* __restrict__ smap,
                     const float* __restrict__ rmap,
                     const int* __restrict__ regions,
                     float* __restrict__ out)
{
    const int tid = threadIdx.x;
    const int w4  = tid & (W4_ - 1);                 // invariant per thread
    const int blockBase = blockIdx.x * (256 * V_);   // float4 index
    const int bc = blockBase >> 14;                  // uniform per block
    const int c  = bc & (C_ - 1);
    const int b  = bc >> 5;
    const int hbase = ((blockBase >> 6) & (H_ - 1)) + (tid >> 6);

    // Hoisted per-k state: y-range and x-predicate (x fixed per thread).
    int ys[K_]; unsigned ylen[K_]; bool xok[K_];
    #pragma unroll
    for (int k = 0; k < K_; ++k) {
        ys[k]   = __ldg(&regions[(b * K_ + k) * 2 + 0]) << 6;
        int xs4 =  __ldg(&regions[(b * K_ + k) * 2 + 1]) << 4;   // float4 units
        ylen[k] = (unsigned)(min(ys[k] + 192, H_) - ys[k]);
        xok[k]  = (unsigned)(w4 - xs4) < (unsigned)(min(xs4 + 48, W4_) - xs4);
    }

    // Per-k source base pointers with w4 folded in.
    const float4* s4 = reinterpret_cast<const float4*>(smap) + (size_t)bc * PLANE4 + w4;
    const float4* r4 = reinterpret_cast<const float4*>(rmap)
                     + ((size_t)(b * K_) * C_ + c) * PLANE4 + w4;

    float4 v[V_];
    #pragma unroll
    for (int i = 0; i < V_; ++i) {
        int h = hbase + 4 * i;
        const float4* p = s4;
        #pragma unroll
        for (int k = 0; k < K_; ++k) {               // ascending: last write wins
            bool inside = xok[k] & ((unsigned)(h - ys[k]) < ylen[k]);
            const float4* pk = r4 + (size_t)k * (C_ * PLANE4);
            p = inside ? pk : p;
        }
        v[i] = __ldg(p + h * W4_);                   // MLP=4, front-batched
    }

    float4* o4 = reinterpret_cast<float4*>(out) + blockBase + tid;
    #pragma unroll
    for (int i = 0; i < V_; ++i) {
        v[i].x = fast_sigmoid(v[i].x);
        v[i].y = fast_sigmoid(v[i].y);
        v[i].z = fast_sigmoid(v[i].z);
        v[i].w = fast_sigmoid(v[i].w);
        stcs4(&o4[i * 256], v[i]);
    }
}

extern "C" void kernel_launch(void* const* d_in, const int* in_sizes, int n_in,
                              void* d_out, int out_size)
{
    const float* smap    = (const float*)d_in[0];
    const float* rmap    = (const float*)d_in[1];
    const int*   regions = (const int*)d_in[2];
    float*       out     = (float*)d_out;

    const int total4  = B_ * C_ * H_ * W_ / 4;       // 4,194,304 float4s
    const int threads = 256;
    const int blocks  = total4 / (threads * V_);     // 4096
    feature_fuser_kernel<<<blocks, threads>>>(smap, rmap, regions, out);
}

// round 9
// speedup vs baseline: 1.1198x; 1.0311x over previous
#include <cuda_runtime.h>

// FeatureFuser: out = sigmoid( last-write-wins(sampling_map, refined[k] over window_k) )
// B=8, TOP_K=4, C=32, H=W=256, GRID=4 (cell 64x64), WINDOW=3 cells (192x192, clipped).
//
// Per output pixel exactly one source is read: refined[b, k_win, c, h, w] where
// k_win = max k whose window contains (h,w), else sampling_map[b,c,h,w].
//
// R9: cp.async (LDGSTS) staging through SMEM decouples MLP from registers:
// 8 in-flight 16B copies per thread (4 KB/warp in flight) at ~24 regs, vs the
// register-held version where V_=8 cost 42 regs and halved occupancy (R6).
// Two commit groups (stages 0-3, 4-7) give coarse copy/compute overlap with
// constant-immediate wait_group. No __syncthreads: each thread consumes only
// its own copied bytes (cp.async completion is per-thread via wait_group).
//
// Warp-stride addressing keeps every cp.async / STG.128 warp-coalesced (512B).
// w4 = tid & 63 invariant per thread -> x-predicates and base pointers hoisted.
// Output stores st.global.cs (evict-first): output never re-read; preserves
// source residency in L2 (R8: reads are ~80% L2-served in steady state).
//
// regions arrive as int32 (JAX x64 disabled downcasts the int64 request).

#define B_      8
#define K_      4
#define C_      32
#define H_      256
#define W_      256
#define W4_     (W_/4)
#define PLANE4  (H_*W_/4)      // 16384 float4s per (b,c) plane
#define V_      8              // pipeline stages (float4s per thread)

__device__ __forceinline__ float fast_sigmoid(float x) {
    float t;
    asm("tanh.approx.f32 %0, %1;" : "=f"(t) : "f"(0.5f * x));
    return fmaf(0.5f, t, 0.5f);
}

__device__ __forceinline__ void stcs4(float4* p, float4 v) {
    asm volatile("st.global.cs.v4.f32 [%0], {%1,%2,%3,%4};"
                 :: "l"(p), "f"(v.x), "f"(v.y), "f"(v.z), "f"(v.w) : "memory");
}

__device__ __forceinline__ void cp16(float4* smem_dst, const float4* gsrc) {
    unsigned s = (unsigned)__cvta_generic_to_shared(smem_dst);
    asm volatile("cp.async.cg.shared.global [%0], [%1], 16;"
                 :: "r"(s), "l"(gsrc) : "memory");
}

__global__ void __launch_bounds__(256)
feature_fuser_kernel(const float* __restrict__ smap,
                     const float* __restrict__ rmap,
                     const int* __restrict__ regions,
                     float* __restrict__ out)
{
    __shared__ float4 stage[V_ * 256];               // 32 KB -> 7 blocks/SM

    const int tid = threadIdx.x;
    const int w4  = tid & (W4_ - 1);                 // invariant per thread
    const int blockBase = blockIdx.x * (256 * V_);   // float4 index
    const int bc = blockBase >> 14;                  // uniform per block
    const int c  = bc & (C_ - 1);
    const int b  = bc >> 5;
    const int hbase = ((blockBase >> 6) & (H_ - 1)) + (tid >> 6);

    // Hoisted per-k state: y-range and x-predicate (x fixed per thread).
    int ys[K_]; unsigned ylen[K_]; bool xok[K_];
    #pragma unroll
    for (int k = 0; k < K_; ++k) {
        ys[k]   = __ldg(&regions[(b * K_ + k) * 2 + 0]) << 6;
        int xs4 =  __ldg(&regions[(b * K_ + k) * 2 + 1]) << 4;   // float4 units
        ylen[k] = (unsigned)(min(ys[k] + 192, H_) - ys[k]);
        xok[k]  = (unsigned)(w4 - xs4) < (unsigned)(min(xs4 + 48, W4_) - xs4);
    }

    // Per-k source base pointers with w4 folded in.
    const float4* s4 = reinterpret_cast<const float4*>(smap) + (size_t)bc * PLANE4 + w4;
    const float4* r4 = reinterpret_cast<const float4*>(rmap)
                     + ((size_t)(b * K_) * C_ + c) * PLANE4 + w4;

    // Issue all 8 async copies (two commit groups of 4).
    #pragma unroll
    for (int i = 0; i < V_; ++i) {
        int h = hbase + 4 * i;
        const float4* p = s4;
        #pragma unroll
        for (int k = 0; k < K_; ++k) {               // ascending: last write wins
            bool inside = xok[k] & ((unsigned)(h - ys[k]) < ylen[k]);
            const float4* pk = r4 + (size_t)k * (C_ * PLANE4);
            p = inside ? pk : p;
        }
        cp16(&stage[i * 256 + tid], p + h * W4_);
        if (i == 3) asm volatile("cp.async.commit_group;" ::: "memory");
    }
    asm volatile("cp.async.commit_group;" ::: "memory");

    float4* o4 = reinterpret_cast<float4*>(out) + blockBase + tid;

    // Consume group 0 (stages 0-3) while group 1 is still in flight.
    asm volatile("cp.async.wait_group 1;" ::: "memory");
    #pragma unroll
    for (int i = 0; i < 4; ++i) {
        float4 v = stage[i * 256 + tid];
        v.x = fast_sigmoid(v.x); v.y = fast_sigmoid(v.y);
        v.z = fast_sigmoid(v.z); v.w = fast_sigmoid(v.w);
        stcs4(&o4[i * 256], v);
    }

    // Consume group 1 (stages 4-7).
    asm volatile("cp.async.wait_group 0;" ::: "memory");
    #pragma unroll
    for (int i = 4; i < V_; ++i) {
        float4 v = stage[i * 256 + tid];
        v.x = fast_sigmoid(v.x); v.y = fast_sigmoid(v.y);
        v.z = fast_sigmoid(v.z); v.w = fast_sigmoid(v.w);
        stcs4(&o4[i * 256], v);
    }
}

extern "C" void kernel_launch(void* const* d_in, const int* in_sizes, int n_in,
                              void* d_out, int out_size)
{
    const float* smap    = (const float*)d_in[0];
    const float* rmap    = (const float*)d_in[1];
    const int*   regions = (const int*)d_in[2];
    float*       out     = (float*)d_out;

    const int total4  = B_ * C_ * H_ * W_ / 4;       // 4,194,304 float4s
    const int threads = 256;
    const int blocks  = total4 / (threads * V_);     // 2048
    feature_fuser_kernel<<<blocks, threads>>>(smap, rmap, regions, out);
}